// round 10
// baseline (speedup 1.0000x reference)
#include <cuda_runtime.h>
#include <cuda_fp16.h>

#define B_   8
#define TE_  512
#define TD_  128
#define H_   256
#define ESPLIT 4

// Scratch (allocation-free rule: device globals)
__device__ float g_ep[B_ * TE_ * H_];      // enc @ W_a   [B,TE,H]
__device__ float g_dp[B_ * TD_ * H_];      // dec @ U_a   [B,TD,H]
__device__ float g_score[B_ * TD_ * TE_];  // raw scores  [B,TD,TE]
__device__ float g_part[ESPLIT][B_ * TD_ * H_];  // ctx partial sums (4 MB)

__device__ __forceinline__ unsigned tanh2_fast(unsigned x2) {
    unsigned y2;
    asm("tanh.approx.f16x2 %0, %1;" : "=r"(y2) : "r"(x2));
    return y2;
}

// Packed fp32 pair FMA (Blackwell FFMA2): d = a*b + d, two lanes at once.
__device__ __forceinline__ void ffma2(unsigned long long& d,
                                      unsigned long long a,
                                      unsigned long long b) {
    asm("fma.rn.f32x2 %0, %1, %2, %0;" : "+l"(d) : "l"(a), "l"(b));
}
__device__ __forceinline__ unsigned long long rep2(float x) {
    unsigned long long p;
    asm("mov.b64 %0, {%1, %1};" : "=l"(p) : "r"(__float_as_uint(x)));
    return p;
}
__device__ __forceinline__ unsigned long long pk2(float lo, float hi) {
    unsigned long long p;
    asm("mov.b64 %0, {%1, %2};" : "=l"(p)
        : "r"(__float_as_uint(lo)), "r"(__float_as_uint(hi)));
    return p;
}
__device__ __forceinline__ void unpk2(unsigned long long v,
                                      float& lo, float& hi) {
    unsigned a, b;
    asm("mov.b64 {%0, %1}, %2;" : "=r"(a), "=r"(b) : "l"(v));
    lo = __uint_as_float(a);
    hi = __uint_as_float(b);
}
__device__ __forceinline__ unsigned packh2(float a, float b) {
    __half2 h = __floats2half2_rn(a, b);   // lo = a, hi = b
    return *(unsigned*)&h;
}

// ---------------------------------------------------------------------------
// Projection GEMM, FFMA2 edition. (unchanged)
// BM=64, BN=32, BK=16, 128 threads. Blocks [0,512)=enc@Wa, [512,640)=dec@Ua.
// ---------------------------------------------------------------------------
__global__ __launch_bounds__(128) void proj_kernel(
    const float* __restrict__ enc, const float* __restrict__ dec,
    const float* __restrict__ Wa,  const float* __restrict__ Ua)
{
    __shared__ float As[16][68];
    __shared__ float Ws[16][36];

    const int bid = blockIdx.x;
    const float* __restrict__ A;
    const float* __restrict__ W;
    float* __restrict__ P;
    int bm, bn;
    if (bid < 512) {
        A = enc; W = Wa; P = g_ep;
        bm = (bid >> 3) * 64; bn = (bid & 7) * 32;
    } else {
        const int r = bid - 512;
        A = dec; W = Ua; P = g_dp;
        bm = (r >> 3) * 64; bn = (r & 7) * 32;
    }

    const int t  = threadIdx.x;
    const int tx = t & 15;
    const int ty = t >> 4;

    unsigned long long acc[4][2];
#pragma unroll
    for (int i = 0; i < 4; i++) { acc[i][0] = 0ull; acc[i][1] = 0ull; }

    const int rowA = t >> 2;
    const int kqA  = t & 3;
    const int kkW  = t >> 3;
    const int nqW  = t & 7;

    float4 a0 = *(const float4*)&A[(bm + rowA) * H_ + kqA * 4];
    float4 a1 = *(const float4*)&A[(bm + rowA + 32) * H_ + kqA * 4];
    float4 wv = *(const float4*)&W[kkW * H_ + bn + nqW * 4];

    for (int k0 = 0; k0 < H_; k0 += 16) {
        As[kqA * 4 + 0][rowA] = a0.x;
        As[kqA * 4 + 1][rowA] = a0.y;
        As[kqA * 4 + 2][rowA] = a0.z;
        As[kqA * 4 + 3][rowA] = a0.w;
        As[kqA * 4 + 0][rowA + 32] = a1.x;
        As[kqA * 4 + 1][rowA + 32] = a1.y;
        As[kqA * 4 + 2][rowA + 32] = a1.z;
        As[kqA * 4 + 3][rowA + 32] = a1.w;
        *(float4*)&Ws[kkW][nqW * 4] = wv;
        __syncthreads();

        if (k0 + 16 < H_) {
            a0 = *(const float4*)&A[(bm + rowA) * H_ + k0 + 16 + kqA * 4];
            a1 = *(const float4*)&A[(bm + rowA + 32) * H_ + k0 + 16 + kqA * 4];
            wv = *(const float4*)&W[(k0 + 16 + kkW) * H_ + bn + nqW * 4];
        }

#pragma unroll
        for (int k = 0; k < 16; k++) {
            ulonglong2 aP = *(const ulonglong2*)&As[k][ty * 8];
            ulonglong2 aQ = *(const ulonglong2*)&As[k][ty * 8 + 4];
            float2 bv = *(const float2*)&Ws[k][tx * 2];
            unsigned long long b0 = rep2(bv.x);
            unsigned long long b1 = rep2(bv.y);
            ffma2(acc[0][0], aP.x, b0);  ffma2(acc[0][1], aP.x, b1);
            ffma2(acc[1][0], aP.y, b0);  ffma2(acc[1][1], aP.y, b1);
            ffma2(acc[2][0], aQ.x, b0);  ffma2(acc[2][1], aQ.x, b1);
            ffma2(acc[3][0], aQ.y, b0);  ffma2(acc[3][1], aQ.y, b1);
        }
        __syncthreads();
    }

#pragma unroll
    for (int i2 = 0; i2 < 4; i2++) {
        float l0, h0f, l1, h1f;
        unpk2(acc[i2][0], l0, h0f);
        unpk2(acc[i2][1], l1, h1f);
        float2 r0 = {l0, l1};
        float2 r1 = {h0f, h1f};
        *(float2*)&P[(bm + ty * 8 + i2 * 2    ) * H_ + bn + tx * 2] = r0;
        *(float2*)&P[(bm + ty * 8 + i2 * 2 + 1) * H_ + bn + tx * 2] = r1;
    }
}

// ---------------------------------------------------------------------------
// Score kernel, f16x2 tanh edition (unchanged from R9).
// Grid: (TE/32, TD/8, B) = 2048 blocks, 256 threads.
// ---------------------------------------------------------------------------
__global__ __launch_bounds__(256) void score_kernel(const float* __restrict__ V)
{
    __shared__ unsigned sET2[32][33];            // [h-pair][e] f16x2
    __shared__ unsigned sdp2[8][128];            // dp rows as f16x2
    __shared__ unsigned long long sVp[128];      // V as f32x2 pairs

    const int t    = threadIdx.x;
    const int lane = t & 31;
    const int w    = t >> 5;
    const int b    = blockIdx.z;
    const int d0   = blockIdx.y * 8;
    const int e0   = blockIdx.x * 32;

    {
        const float4* dpsrc = (const float4*)(g_dp + (b * TD_ + d0) * H_);
#pragma unroll
        for (int i = 0; i < 2; i++) {
            int idx = t + i * 256;
            int row = idx >> 6, colq = idx & 63;
            float4 v = dpsrc[row * 64 + colq];
            sdp2[row][colq * 2]     = packh2(v.x, v.y);
            sdp2[row][colq * 2 + 1] = packh2(v.z, v.w);
        }
        if (t < 128) {
            float2 vv = ((const float2*)V)[t];
            sVp[t] = pk2(vv.x, vv.y);
        }
    }

    const float* ep = g_ep + b * TE_ * H_;
    unsigned long long acc = 0ull;

    for (int ht = 0; ht < 4; ++ht) {
        __syncthreads();
#pragma unroll
        for (int i = 0; i < 2; i++) {
            int idx = t + i * 256;
            int e_row = idx >> 4, hq = idx & 15;
            float4 v = *(const float4*)&ep[(e0 + e_row) * H_ + ht * 64 + hq * 4];
            sET2[hq * 2    ][e_row] = packh2(v.x, v.y);
            sET2[hq * 2 + 1][e_row] = packh2(v.z, v.w);
        }
        __syncthreads();

        const unsigned* dprow = &sdp2[w][ht * 32];
        const unsigned long long* vrow = &sVp[ht * 32];
#pragma unroll
        for (int hp = 0; hp < 32; ++hp) {
            unsigned ep2 = sET2[hp][lane];
            unsigned dp2 = dprow[hp];
            __half2 arg = __hadd2(*(__half2*)&ep2, *(__half2*)&dp2);
            unsigned t2 = tanh2_fast(*(unsigned*)&arg);
            __half2 th = *(__half2*)&t2;
            float lo = __low2float(th);
            float hi = __high2float(th);
            ffma2(acc, vrow[hp], pk2(lo, hi));
        }
    }

    float slo, shi;
    unpk2(acc, slo, shi);
    g_score[(b * TD_ + d0 + w) * TE_ + e0 + lane] = slo + shi;
}

// ---------------------------------------------------------------------------
// Fused softmax + context partials.
// Grid: ((H/64)*ESPLIT, TD/32, B) = (16, 4, 8) = 512 blocks, 256 threads.
// Each block: softmax over FULL e-row for its 32 d-rows (redundant across hq,
// bit-identical -> deterministic), keeps normalized chunk es in sWt.
// Blocks with hq==es write the global weights chunk. MAC body = R6 ctx.
// Lane softmax layout: e = 4*lane + 128*i, so register v[es] IS chunk es.
// ---------------------------------------------------------------------------
__global__ __launch_bounds__(256) void ctx_fused_kernel(
    const float* __restrict__ enc, float* __restrict__ out)
{
    __shared__ float sE[128][64];    // 32 KB: enc slab [e][h]
    __shared__ float sWt[32][128];   // 16 KB: normalized weights chunk [d][e]

    const int t    = threadIdx.x;
    const int lane = t & 31;
    const int w    = t >> 5;
    const int b    = blockIdx.z;
    const int d0   = blockIdx.y * 32;
    const int hq   = blockIdx.x & 3;        // h tile
    const int es   = blockIdx.x >> 2;       // e split (0..3)
    const int h0   = hq * 64;
    const int e0   = es * 128;

    const float* enc_b = enc + b * TE_ * H_;

    // ---- in-block softmax: warp w handles local rows {w, w+8, w+16, w+24} ----
#pragma unroll
    for (int r4 = 0; r4 < 4; ++r4) {
        const int lw = w + 8 * r4;
        const float4* srow = (const float4*)(g_score + (b * TD_ + d0 + lw) * TE_);
        float4 v[4];
        float m = -1e30f;
#pragma unroll
        for (int i = 0; i < 4; i++) {
            v[i] = srow[lane + 32 * i];
            m = fmaxf(m, fmaxf(fmaxf(v[i].x, v[i].y), fmaxf(v[i].z, v[i].w)));
        }
#pragma unroll
        for (int o = 16; o > 0; o >>= 1)
            m = fmaxf(m, __shfl_xor_sync(0xffffffffu, m, o));
        float sum = 0.f;
#pragma unroll
        for (int i = 0; i < 4; i++) {
            v[i].x = __expf(v[i].x - m);
            v[i].y = __expf(v[i].y - m);
            v[i].z = __expf(v[i].z - m);
            v[i].w = __expf(v[i].w - m);
            sum += v[i].x + v[i].y + v[i].z + v[i].w;
        }
#pragma unroll
        for (int o = 16; o > 0; o >>= 1)
            sum += __shfl_xor_sync(0xffffffffu, sum, o);
        const float inv = __fdividef(1.f, sum);

        // Keep only chunk es (e = 4*lane + 128*es lives in v[es]).
        float4 vn = (es == 0) ? v[0] : (es == 1) ? v[1] : (es == 2) ? v[2] : v[3];
        vn.x *= inv; vn.y *= inv; vn.z *= inv; vn.w *= inv;
        *(float4*)&sWt[lw][lane * 4] = vn;
        if (hq == es) {
            float* gout = out + (size_t)B_ * TD_ * H_ +
                          (b * TD_ + d0 + lw) * TE_ + e0;
            *(float4*)&gout[lane * 4] = vn;
        }
    }

    // ---- stage sE: 128 e-rows x 64 h ----
#pragma unroll
    for (int i = 0; i < 8; i++) {
        int idx = t + i * 256;               // 2048 float4 slots
        int row = idx >> 4, col = (idx & 15) * 4;
        *(float4*)&sE[row][col] =
            *(const float4*)&enc_b[(e0 + row) * H_ + h0 + col];
    }
    __syncthreads();

    // ---- MAC body (identical to R6 ctx) ----
    unsigned long long acc[4] = {0ull, 0ull, 0ull, 0ull};

#pragma unroll 2
    for (int e4 = 0; e4 < 32; ++e4) {
        float4 wr0 = *(const float4*)&sWt[w     ][e4 * 4];
        float4 wr1 = *(const float4*)&sWt[w +  8][e4 * 4];
        float4 wr2 = *(const float4*)&sWt[w + 16][e4 * 4];
        float4 wr3 = *(const float4*)&sWt[w + 24][e4 * 4];
        const float* f0 = (const float*)&wr0;
        const float* f1 = (const float*)&wr1;
        const float* f2 = (const float*)&wr2;
        const float* f3 = (const float*)&wr3;
#pragma unroll
        for (int j = 0; j < 4; j++) {
            unsigned long long ev =
                *(const unsigned long long*)&sE[e4 * 4 + j][lane * 2];
            ffma2(acc[0], rep2(f0[j]), ev);
            ffma2(acc[1], rep2(f1[j]), ev);
            ffma2(acc[2], rep2(f2[j]), ev);
            ffma2(acc[3], rep2(f3[j]), ev);
        }
    }

#pragma unroll
    for (int r = 0; r < 4; r++) {
        float lo, hi;
        unpk2(acc[r], lo, hi);
        float2 o = {lo, hi};
        *(float2*)&g_part[es][(b * TD_ + d0 + w + 8 * r) * H_ + h0 + lane * 2] = o;
    }
}

// ---------------------------------------------------------------------------
// Combine: out = (p0+p1)+(p2+p3), fixed order (deterministic).
// 262144 floats = 65536 float4; grid 256 x 256 threads.
// ---------------------------------------------------------------------------
__global__ __launch_bounds__(256) void combine_kernel(float* __restrict__ out)
{
    const int i = blockIdx.x * 256 + threadIdx.x;   // float4 index
    const float4 p0 = ((const float4*)g_part[0])[i];
    const float4 p1 = ((const float4*)g_part[1])[i];
    const float4 p2 = ((const float4*)g_part[2])[i];
    const float4 p3 = ((const float4*)g_part[3])[i];
    float4 o;
    o.x = (p0.x + p1.x) + (p2.x + p3.x);
    o.y = (p0.y + p1.y) + (p2.y + p3.y);
    o.z = (p0.z + p1.z) + (p2.z + p3.z);
    o.w = (p0.w + p1.w) + (p2.w + p3.w);
    ((float4*)out)[i] = o;
}

// ---------------------------------------------------------------------------
extern "C" void kernel_launch(void* const* d_in, const int* in_sizes, int n_in,
                              void* d_out, int out_size)
{
    const float* enc = (const float*)d_in[0];   // [B,TE,H]
    const float* dec = (const float*)d_in[1];   // [B,TD,H]
    const float* Wa  = (const float*)d_in[2];   // [H,H]
    const float* Ua  = (const float*)d_in[3];   // [H,H]
    const float* Va  = (const float*)d_in[4];   // [H,1]
    float* out = (float*)d_out;                 // context [B,TD,H] then weights [B,TD,TE]

    proj_kernel<<<dim3(640), 128>>>(enc, dec, Wa, Ua);
    score_kernel<<<dim3(TE_ / 32, TD_ / 8, B_), 256>>>(Va);
    ctx_fused_kernel<<<dim3((H_ / 64) * ESPLIT, TD_ / 32, B_), 256>>>(enc, out);
    combine_kernel<<<dim3(256), 256>>>(out);
}